// round 12
// baseline (speedup 1.0000x reference)
#include <cuda_runtime.h>

// 3D SSIM, B=4, 128^3, WIN=7 separable box -> 122^3, mean.
// SINGLE merged launch, software-pipelined:
//   block order A0 A1 B0 A2 B1 A3 B2 B3 (per batch), flag-based dependency.
// A role: R8's fused W+H window sums -> g2q (float4 pack (sx,sy,sxx+syy,sxy)).
// B role: R8's D window sums (ring) + SSIM (paired division) + fused reduce.

#define BATCH 4
#define DD 128
#define HH 128
#define WW 128
#define WO  122
#define WIN 7

#define STRIP  14
#define NSTRIP 9
#define XP 132
#define RP 123
#define GP 128            // g2 row pitch (elements)

#define NA_B 1152         // A blocks per batch = NSTRIP*DD
#define NB_B 466          // B blocks per batch = ceil(8*122*122/256)
#define NB_TOT (4 * NB_B) // 1864
#define PER_BATCH (8 * WO * WO)   // 119072 B threads per batch

__device__ float4 g2q[62464 * GP];     // (b,d,h) rows, pitch 128 -> 128 MB
__device__ int    plane_flag[BATCH * DD];
__device__ double g_part[2048];
__device__ unsigned int g_ctr = 0;

// ---------------------------------------------------------------------------
// A role: fused W+H box sums (exact R8 internals). local = s + d*NSTRIP... (s,d)
// ---------------------------------------------------------------------------
__device__ __forceinline__ void do_A(const float* __restrict__ X,
                                     const float* __restrict__ Y,
                                     int b, int local, float* sm) {
    float*  xs  = sm;                         // [20][XP]
    float*  ys  = sm + 20 * XP;               // [20][XP]
    float4* rw4 = (float4*)(sm + 40 * XP);    // [20][RP]

    const int s  = local % NSTRIP;
    const int d  = local / NSTRIP;
    const int h0 = s * STRIP;
    const int nout = min(STRIP, WO - h0);     // 14 (last strip: 10)
    const int nin  = nout + 6;                // 20 (last strip: 16)
    const int tid  = threadIdx.x;

    const size_t gbase = ((size_t)(b * DD + d) * HH + h0) * WW;
    for (int i = tid; i < nin * 32; i += 256) {
        const int r = i >> 5, v = (i & 31) << 2;
        const float4 xv = *(const float4*)(X + gbase + (size_t)r * WW + v);
        const float4 yv = *(const float4*)(Y + gbase + (size_t)r * WW + v);
        *(float4*)(xs + r * XP + v) = xv;
        *(float4*)(ys + r * XP + v) = yv;
    }
    __syncthreads();

    // W-direction sliding sums: 8 chunks of 16 outputs per row
    {
        const int njobs = nin * 8;
        for (int job = tid; job < njobs; job += 256) {
            const int r   = job % nin;
            const int ch  = job / nin;
            const int wst = ch * 16;
            const int nw  = (ch == 7) ? 10 : 16;

            float xv[24], yv[24];
#pragma unroll
            for (int k = 0; k < 6; k++) {
                if (wst + 4 * k < WW) {
                    const float4 xq = *(const float4*)(xs + r * XP + wst + 4 * k);
                    const float4 yq = *(const float4*)(ys + r * XP + wst + 4 * k);
                    xv[4*k] = xq.x; xv[4*k+1] = xq.y; xv[4*k+2] = xq.z; xv[4*k+3] = xq.w;
                    yv[4*k] = yq.x; yv[4*k+1] = yq.y; yv[4*k+2] = yq.z; yv[4*k+3] = yq.w;
                } else {
#pragma unroll
                    for (int u = 0; u < 4; u++) { xv[4*k+u] = 0.f; yv[4*k+u] = 0.f; }
                }
            }

            float s0 = 0.f, s1 = 0.f, s2 = 0.f, s4 = 0.f;
#pragma unroll
            for (int j = 0; j < 6; j++) {
                s0 += xv[j]; s1 += yv[j];
                s2 += xv[j] * xv[j] + yv[j] * yv[j];
                s4 += xv[j] * yv[j];
            }
#pragma unroll
            for (int o = 0; o < 16; o++) {
                if (o < nw) {
                    s0 += xv[o + 6]; s1 += yv[o + 6];
                    s2 += xv[o + 6] * xv[o + 6] + yv[o + 6] * yv[o + 6];
                    s4 += xv[o + 6] * yv[o + 6];
                    rw4[r * RP + wst + o] = make_float4(s0, s1, s2, s4);
                    s0 -= xv[o]; s1 -= yv[o];
                    s2 -= xv[o] * xv[o] + yv[o] * yv[o];
                    s4 -= xv[o] * yv[o];
                }
            }
        }
    }
    __syncthreads();

    // H-direction sliding sums with 7-deep register history
    for (int w = tid; w < WO; w += 256) {
        const size_t obase = ((size_t)(b * DD + d) * WO + h0) * GP + w;
        float4 hist[7];
        float4 acc = make_float4(0.f, 0.f, 0.f, 0.f);
#pragma unroll
        for (int r = 0; r < 20; r++) {
            if (r < nin) {
                const float4 v = rw4[r * RP + w];
                acc.x += v.x; acc.y += v.y; acc.z += v.z; acc.w += v.w;
                if (r >= 6) {
                    const int o = r - 6;
                    g2q[obase + (size_t)o * GP] = acc;
                    const float4 h7 = hist[o % 7];
                    acc.x -= h7.x; acc.y -= h7.y; acc.z -= h7.z; acc.w -= h7.w;
                }
                hist[r % 7] = v;
            }
        }
    }

    // publish: this (b,d) plane has one more strip complete
    __syncthreads();
    if (tid == 0) {
        __threadfence();
        atomicAdd(&plane_flag[b * DD + d], 1);
    }
}

// ---------------------------------------------------------------------------
// B role: D window sums + SSIM (float4 ring, paired division) + fused reduce.
// ---------------------------------------------------------------------------
template <int NST>
__device__ __forceinline__ float run_chunk(size_t base, float C1, float C2) {
    constexpr float inv = 1.0f / 343.0f;
    constexpr float cov = 343.0f / 342.0f;
    const size_t ds = (size_t)WO * GP;

    float4 ring[7];
    float4 acc = make_float4(0.f, 0.f, 0.f, 0.f);
    float  local = 0.f;
    float  pn = 0.f, pd = 1.f;

#pragma unroll
    for (int j = 0; j < NST; j++) {
        const float4 v = __ldg(&g2q[base + (size_t)j * ds]);
        acc.x += v.x; acc.y += v.y; acc.z += v.z; acc.w += v.w;
        if (j >= 6) {
            const float ux  = acc.x * inv;
            const float uy  = acc.y * inv;
            const float uss = acc.z * inv;
            const float uxy = acc.w * inv;
            const float sq  = ux * ux + uy * uy;
            const float vxy = cov * (uxy - ux * uy);
            const float vs  = cov * (uss - sq);
            const float A1 = 2.f * ux * uy + C1;
            const float A2 = 2.f * vxy + C2;
            const float B1 = sq + C1;
            const float B2 = vs + C2;
            const float n  = A1 * A2;
            const float dn = B1 * B2;
            if (((j - 6) & 1) == 0) {
                pn = n; pd = dn;
            } else {
                local += __fdividef(n * pd + pn * dn, dn * pd);
            }
            const float4 o4 = ring[(j - 6) % 7];
            acc.x -= o4.x; acc.y -= o4.y; acc.z -= o4.z; acc.w -= o4.w;
        }
        ring[j % 7] = v;
    }
    return local;
}

__device__ __forceinline__ void do_B(const float* __restrict__ dr,
                                     float* __restrict__ out,
                                     int b, int local, float* sm) {
    const int tid = threadIdx.x;
    const int idx = local * 256 + tid;            // within batch b

    // --- wait for the g2 planes this block needs ---
    {
        const int i0 = local * 256;
        const int i1 = min(i0 + 255, PER_BATCH - 1);
        const int c0 = i0 / (WO * WO);
        const int c1 = i1 / (WO * WO);
        const int dlo = c0 * 16;
        const int dhi = min(c1 * 16 + 21, DD - 1);
        if (tid == 0) {
            for (int d = dlo; d <= dhi; d++) {
                while (atomicAdd(&plane_flag[b * DD + d], 0) < NSTRIP)
                    __nanosleep(64);
            }
            __threadfence();
        }
        __syncthreads();
    }

    float local_s = 0.f;
    if (idx < PER_BATCH) {
        const int w = idx % WO;
        const int h = (idx / WO) % WO;
        const int c = idx / (WO * WO);
        const int d0 = c * 16;

        const float r  = __ldg(&dr[b]);
        const float C1 = (0.01f * r) * (0.01f * r);
        const float C2 = (0.03f * r) * (0.03f * r);

        const size_t base = ((size_t)(b * DD + d0) * WO + h) * GP + w;

        if (c < 7) local_s = run_chunk<22>(base, C1, C2);   // 16 outputs
        else       local_s = run_chunk<16>(base, C1, C2);   // 10 outputs
    }

    double* red = (double*)sm;
    red[tid] = (double)local_s;
    __syncthreads();
#pragma unroll
    for (int s = 128; s > 0; s >>= 1) {
        if (tid < s) red[tid] += red[tid + s];
        __syncthreads();
    }

    __shared__ bool is_last;
    const int gb = b * NB_B + local;              // global B-block index
    if (tid == 0) {
        g_part[gb] = red[0];
        __threadfence();
        const unsigned int t = atomicAdd(&g_ctr, 1u);
        is_last = (t == NB_TOT - 1);
    }
    __syncthreads();

    if (is_last) {
        __threadfence();
        double v = 0.0;
        for (int i = tid; i < NB_TOT; i += 256) v += g_part[i];
        red[tid] = v;
        __syncthreads();
#pragma unroll
        for (int s = 128; s > 0; s >>= 1) {
            if (tid < s) red[tid] += red[tid + s];
            __syncthreads();
        }
        // reset flags + counter for the next graph replay
        for (int i = tid; i < BATCH * DD; i += 256) plane_flag[i] = 0;
        if (tid == 0) {
            const double cnt = (double)BATCH * WO * WO * WO;
            out[0] = (float)(red[0] / cnt);
            atomicExch(&g_ctr, 0u);
        }
    }
}

// ---------------------------------------------------------------------------
// Merged kernel: block order A0 A1 B0 A2 B1 A3 B2 B3.
// ---------------------------------------------------------------------------
__global__ void __launch_bounds__(256, 3)
ssim_pipelined(const float* __restrict__ X, const float* __restrict__ Y,
               const float* __restrict__ dr, float* __restrict__ out) {
    extern __shared__ float sm[];
    const int bid = blockIdx.x;

    int role, b, local;
    if      (bid < 1152) { role = 0; b = 0; local = bid;        }
    else if (bid < 2304) { role = 0; b = 1; local = bid - 1152; }
    else if (bid < 2770) { role = 1; b = 0; local = bid - 2304; }
    else if (bid < 3922) { role = 0; b = 2; local = bid - 2770; }
    else if (bid < 4388) { role = 1; b = 1; local = bid - 3922; }
    else if (bid < 5540) { role = 0; b = 3; local = bid - 4388; }
    else if (bid < 6006) { role = 1; b = 2; local = bid - 5540; }
    else                 { role = 1; b = 3; local = bid - 6006; }

    if (role == 0) do_A(X, Y, b, local, sm);
    else           do_B(dr, out, b, local, sm);
}

extern "C" void kernel_launch(void* const* d_in, const int* in_sizes, int n_in,
                              void* d_out, int out_size) {
    const float* X  = (const float*)d_in[0];
    const float* Y  = (const float*)d_in[1];
    const float* dr = (const float*)d_in[2];
    float* out = (float*)d_out;

    const int smem = (40 * XP) * (int)sizeof(float) + 20 * RP * (int)sizeof(float4); // 60,480 B
    cudaFuncSetAttribute(ssim_pipelined, cudaFuncAttributeMaxDynamicSharedMemorySize, smem);

    const int grid = 4 * NA_B + NB_TOT;   // 4608 + 1864 = 6472
    ssim_pipelined<<<grid, 256, smem>>>(X, Y, dr, out);
}

// round 13
// speedup vs baseline: 1.4807x; 1.4807x over previous
#include <cuda_runtime.h>

// 3D SSIM, B=4, 128^3, WIN=7 separable box -> 122^3, mean.
// Intermediate: ONE float4 per voxel (sx, sy, sxx+syy, sxy), pitch 128.
// Kernel A: R8 fused W+H window sums (staged, 16-wide W chunks, H reg-ring).
// Kernel B: D window sums with SMEM ring (reg relief -> 5 blk/SM), paired-div SSIM,
//           fused deterministic reduce.

#define BATCH 4
#define DD 128
#define HH 128
#define WW 128
#define WO  122
#define WIN 7

#define STRIP  14
#define NSTRIP 9
#define XP 132
#define RP 123
#define GP 128            // g2 row pitch (elements)

// g2 rows: (b,d,h) = 4*128*122 = 62,464 rows, pitch 128 float4 -> 128 MB.
__device__ float4 g2q[62464 * GP];
__device__ double g_part[2048];
__device__ unsigned int g_ctr = 0;

// ---------------------------------------------------------------------------
// Kernel A: fused W+H box sums, 4-quantity pack (exact R8).
// grid = b(4)*d(128)*strip(9) = 4608 blocks, 256 threads, smem 60,480 B.
// ---------------------------------------------------------------------------
__global__ void __launch_bounds__(256, 3)
fused_wh(const float* __restrict__ X, const float* __restrict__ Y) {
    extern __shared__ float sm[];
    float*  xs  = sm;                         // [20][XP]
    float*  ys  = sm + 20 * XP;               // [20][XP]
    float4* rw4 = (float4*)(sm + 40 * XP);    // [20][RP]

    const int s  = blockIdx.x % NSTRIP;
    const int d  = (blockIdx.x / NSTRIP) % DD;
    const int b  = blockIdx.x / (NSTRIP * DD);
    const int h0 = s * STRIP;
    const int nout = min(STRIP, WO - h0);     // 14 (last strip: 10)
    const int nin  = nout + 6;                // 20 (last strip: 16)
    const int tid  = threadIdx.x;

    const size_t gbase = ((size_t)(b * DD + d) * HH + h0) * WW;
    for (int i = tid; i < nin * 32; i += 256) {
        const int r = i >> 5, v = (i & 31) << 2;
        const float4 xv = *(const float4*)(X + gbase + (size_t)r * WW + v);
        const float4 yv = *(const float4*)(Y + gbase + (size_t)r * WW + v);
        *(float4*)(xs + r * XP + v) = xv;
        *(float4*)(ys + r * XP + v) = yv;
    }
    __syncthreads();

    // --- W-direction sliding sums: (sx, sy, sxx+syy, sxy) ---
    {
        const int njobs = nin * 8;
        for (int job = tid; job < njobs; job += 256) {
            const int r   = job % nin;
            const int ch  = job / nin;
            const int wst = ch * 16;
            const int nw  = (ch == 7) ? 10 : 16;

            float xv[24], yv[24];
#pragma unroll
            for (int k = 0; k < 6; k++) {
                if (wst + 4 * k < WW) {
                    const float4 xq = *(const float4*)(xs + r * XP + wst + 4 * k);
                    const float4 yq = *(const float4*)(ys + r * XP + wst + 4 * k);
                    xv[4*k] = xq.x; xv[4*k+1] = xq.y; xv[4*k+2] = xq.z; xv[4*k+3] = xq.w;
                    yv[4*k] = yq.x; yv[4*k+1] = yq.y; yv[4*k+2] = yq.z; yv[4*k+3] = yq.w;
                } else {
#pragma unroll
                    for (int u = 0; u < 4; u++) { xv[4*k+u] = 0.f; yv[4*k+u] = 0.f; }
                }
            }

            float s0 = 0.f, s1 = 0.f, s2 = 0.f, s4 = 0.f;
#pragma unroll
            for (int j = 0; j < 6; j++) {
                s0 += xv[j]; s1 += yv[j];
                s2 += xv[j] * xv[j] + yv[j] * yv[j];
                s4 += xv[j] * yv[j];
            }
#pragma unroll
            for (int o = 0; o < 16; o++) {
                if (o < nw) {
                    s0 += xv[o + 6]; s1 += yv[o + 6];
                    s2 += xv[o + 6] * xv[o + 6] + yv[o + 6] * yv[o + 6];
                    s4 += xv[o + 6] * yv[o + 6];
                    rw4[r * RP + wst + o] = make_float4(s0, s1, s2, s4);
                    s0 -= xv[o]; s1 -= yv[o];
                    s2 -= xv[o] * xv[o] + yv[o] * yv[o];
                    s4 -= xv[o] * yv[o];
                }
            }
        }
    }
    __syncthreads();

    // --- H-direction sliding sums with 7-deep register history ---
    for (int w = tid; w < WO; w += 256) {
        const size_t obase = ((size_t)(b * DD + d) * WO + h0) * GP + w;
        float4 hist[7];
        float4 acc = make_float4(0.f, 0.f, 0.f, 0.f);
#pragma unroll
        for (int r = 0; r < 20; r++) {
            if (r < nin) {
                const float4 v = rw4[r * RP + w];
                acc.x += v.x; acc.y += v.y; acc.z += v.z; acc.w += v.w;
                if (r >= 6) {
                    const int o = r - 6;
                    g2q[obase + (size_t)o * GP] = acc;
                    const float4 h7 = hist[o % 7];
                    acc.x -= h7.x; acc.y -= h7.y; acc.z -= h7.z; acc.w -= h7.w;
                }
                hist[r % 7] = v;
            }
        }
    }
}

// ---------------------------------------------------------------------------
// Kernel B: branch-free D window sums + SSIM (SMEM ring, paired division).
// ---------------------------------------------------------------------------
template <int NST>
__device__ __forceinline__ float run_chunk(size_t base, float C1, float C2,
                                           float4* ring) {
    constexpr float inv = 1.0f / 343.0f;
    constexpr float cov = 343.0f / 342.0f;
    const size_t ds = (size_t)WO * GP;

    float4 acc = make_float4(0.f, 0.f, 0.f, 0.f);
    float  local = 0.f;
    float  pn = 0.f, pd = 1.f;

#pragma unroll
    for (int j = 0; j < NST; j++) {
        const float4 v = __ldg(&g2q[base + (size_t)j * ds]);
        acc.x += v.x; acc.y += v.y; acc.z += v.z; acc.w += v.w;
        if (j >= 6) {
            const float ux  = acc.x * inv;      // mean x
            const float uy  = acc.y * inv;      // mean y
            const float uss = acc.z * inv;      // mean (x^2 + y^2)
            const float uxy = acc.w * inv;      // mean xy
            const float sq  = ux * ux + uy * uy;
            const float vxy = cov * (uxy - ux * uy);
            const float vs  = cov * (uss - sq);           // vx + vy
            const float A1 = 2.f * ux * uy + C1;
            const float A2 = 2.f * vxy + C2;
            const float B1 = sq + C1;
            const float B2 = vs + C2;
            const float n  = A1 * A2;
            const float dn = B1 * B2;
            if (((j - 6) & 1) == 0) {
                pn = n; pd = dn;
            } else {
                local += __fdividef(n * pd + pn * dn, dn * pd);
            }
            const float4 o4 = ring[(j - 6) % 7];   // written 6 steps ago
            acc.x -= o4.x; acc.y -= o4.y; acc.z -= o4.z; acc.w -= o4.w;
        }
        ring[j % 7] = v;
    }
    return local;
}

__global__ void __launch_bounds__(256, 5)
pass_d_ssim(const float* __restrict__ dr, float* __restrict__ out) {
    __shared__ float4 ringbuf[256 * 7];   // 28,672 B; per-thread stride 7 (28 words)
    __shared__ double red[256];

    const int tid   = threadIdx.x;
    const int idx   = blockIdx.x * 256 + tid;
    const int total = 8 * BATCH * WO * WO;

    float4* ring = &ringbuf[tid * 7];

    float local = 0.f;
    if (idx < total) {
        const int w = idx % WO;
        const int h = (idx / WO) % WO;
        const int b = (idx / (WO * WO)) % BATCH;
        const int c = idx / (WO * WO * BATCH);

        const int d0 = c * 16;                 // chunks 0..6: 16 outs, chunk 7: 10

        const float r  = __ldg(&dr[b]);
        const float C1 = (0.01f * r) * (0.01f * r);
        const float C2 = (0.03f * r) * (0.03f * r);

        const size_t base = ((size_t)(b * DD + d0) * WO + h) * GP + w;

        if (c < 7) local = run_chunk<22>(base, C1, C2, ring);   // 16 outputs
        else       local = run_chunk<16>(base, C1, C2, ring);   // 10 outputs
    }

    red[tid] = (double)local;
    __syncthreads();
#pragma unroll
    for (int s = 128; s > 0; s >>= 1) {
        if (tid < s) red[tid] += red[tid + s];
        __syncthreads();
    }

    __shared__ bool is_last;
    if (tid == 0) {
        g_part[blockIdx.x] = red[0];
        __threadfence();
        const unsigned int t = atomicAdd(&g_ctr, 1u);
        is_last = (t == gridDim.x - 1);
    }
    __syncthreads();

    if (is_last) {
        __threadfence();
        double v = 0.0;
        for (int i = tid; i < (int)gridDim.x; i += 256) v += g_part[i];
        red[tid] = v;
        __syncthreads();
#pragma unroll
        for (int s = 128; s > 0; s >>= 1) {
            if (tid < s) red[tid] += red[tid + s];
            __syncthreads();
        }
        if (tid == 0) {
            const double cnt = (double)BATCH * WO * WO * WO;
            out[0] = (float)(red[0] / cnt);
            atomicExch(&g_ctr, 0u);   // reset for next graph replay
        }
    }
}

extern "C" void kernel_launch(void* const* d_in, const int* in_sizes, int n_in,
                              void* d_out, int out_size) {
    const float* X  = (const float*)d_in[0];
    const float* Y  = (const float*)d_in[1];
    const float* dr = (const float*)d_in[2];
    float* out = (float*)d_out;

    const int smemA = (40 * XP) * (int)sizeof(float) + 20 * RP * (int)sizeof(float4); // 60,480 B
    cudaFuncSetAttribute(fused_wh, cudaFuncAttributeMaxDynamicSharedMemorySize, smemA);

    fused_wh<<<BATCH * DD * NSTRIP, 256, smemA>>>(X, Y);

    const int totalB = 8 * BATCH * WO * WO;          // 476,288
    const int nblocksB = (totalB + 255) / 256;       // 1861
    pass_d_ssim<<<nblocksB, 256>>>(dr, out);
}